// round 1
// baseline (speedup 1.0000x reference)
#include <cuda_runtime.h>

// RobustPrompt_I — fused graph-prompt pipeline.
// Phases: node norms -> edge cosine+scatter -> node prompt/x_new -> edge prune.

#define NN 100000
#define EE 640000
#define DD 128

#define SIM_THR 0.2f
#define DEG_THR 3.0f
#define PT_THR  0.1f
#define EPS_F   1e-8f

// Scratch (no device allocation allowed; __device__ globals are the sanctioned path)
__device__ float g_inv[NN];   // 1/||x_i||
__device__ float g_c[NN];     // scatter-accumulated edge cosine per dst
__device__ float g_deg[NN];   // in-degree (float, exact for counts < 2^24)
__device__ float g_rn[NN];    // 1/max(||x_new_i||, eps)

// ---------------------------------------------------------------------------
// Kernel 1: per-node inverse norm of x; also zero the scatter accumulators.
// One warp per node, each lane owns one float4 (32*4 = 128 = D).
// ---------------------------------------------------------------------------
__global__ void k_norms(const float* __restrict__ x) {
    int warp = (blockIdx.x * blockDim.x + threadIdx.x) >> 5;
    int lane = threadIdx.x & 31;
    if (warp >= NN) return;
    const float4 v = reinterpret_cast<const float4*>(x + (size_t)warp * DD)[lane];
    float s = v.x * v.x + v.y * v.y + v.z * v.z + v.w * v.w;
#pragma unroll
    for (int o = 16; o; o >>= 1) s += __shfl_xor_sync(0xffffffffu, s, o);
    if (lane == 0) {
        g_inv[warp] = 1.0f / sqrtf(s);   // reference uses x / sqrt(sumsq), no eps
        g_c[warp]   = 0.0f;
        g_deg[warp] = 0.0f;
    }
}

// ---------------------------------------------------------------------------
// Kernel 2: per-edge cosine of raw features, scatter-add to dst node.
// One warp per edge; both rows gathered as coalesced float4 per lane.
// ---------------------------------------------------------------------------
__global__ void k_edge_scatter(const float* __restrict__ x,
                               const int* __restrict__ ei) {
    int warp = (blockIdx.x * blockDim.x + threadIdx.x) >> 5;
    int lane = threadIdx.x & 31;
    if (warp >= EE) return;
    const int r = ei[warp];        // row (src)
    const int c = ei[EE + warp];   // col (dst)
    const float4 a = reinterpret_cast<const float4*>(x + (size_t)r * DD)[lane];
    const float4 b = reinterpret_cast<const float4*>(x + (size_t)c * DD)[lane];
    float s = a.x * b.x + a.y * b.y + a.z * b.z + a.w * b.w;
#pragma unroll
    for (int o = 16; o; o >>= 1) s += __shfl_xor_sync(0xffffffffu, s, o);
    if (lane == 0) {
        const float e = s * g_inv[r] * g_inv[c];
        atomicAdd(&g_c[c], e);
        atomicAdd(&g_deg[c], 1.0f);
    }
}

// ---------------------------------------------------------------------------
// Kernel 3: node prompt selection, x_new = x + final, and ||x_new||.
// One warp per node.
// ---------------------------------------------------------------------------
__global__ void k_node(const float* __restrict__ x,
                       const float* __restrict__ ps,
                       const float* __restrict__ pd,
                       const float* __restrict__ po,
                       float* __restrict__ xout) {
    int warp = (blockIdx.x * blockDim.x + threadIdx.x) >> 5;
    int lane = threadIdx.x & 31;
    if (warp >= NN) return;

    const float c   = g_c[warp];
    const float deg = g_deg[warp];
    // csim = deg>0 ? c/deg : +inf ; inf <= 0.2 is false
    const bool m_sim = (deg > 0.0f) && (c / deg <= SIM_THR);
    const bool m_deg = (deg <= DEG_THR);
    const bool m_oth = !(m_sim || m_deg);

    const float4 vs = reinterpret_cast<const float4*>(ps)[lane];
    const float4 vd = reinterpret_cast<const float4*>(pd)[lane];
    const float4 vo = reinterpret_cast<const float4*>(po)[lane];

    // wo_pad: slot counts toward plen only if the whole prompt row is nonzero
    const bool nz_s = __all_sync(0xffffffffu,
        vs.x != 0.0f && vs.y != 0.0f && vs.z != 0.0f && vs.w != 0.0f);
    const bool nz_d = __all_sync(0xffffffffu,
        vd.x != 0.0f && vd.y != 0.0f && vd.z != 0.0f && vd.w != 0.0f);
    const bool nz_o = __all_sync(0xffffffffu,
        vo.x != 0.0f && vo.y != 0.0f && vo.z != 0.0f && vo.w != 0.0f);

    const int plen = (int)(m_sim && nz_s) + (int)(m_deg && nz_d) + (int)(m_oth && nz_o);

    float4 num = make_float4(0.f, 0.f, 0.f, 0.f);
    if (m_sim) { num.x += vs.x; num.y += vs.y; num.z += vs.z; num.w += vs.w; }
    if (m_deg) { num.x += vd.x; num.y += vd.y; num.z += vd.z; num.w += vd.w; }
    if (m_oth) { num.x += vo.x; num.y += vo.y; num.z += vo.z; num.w += vo.w; }

    // plen in {0,1,2}; 1/1 and 1/2 are exact, so this matches record.sum/plen bitwise.
    const float ip = (plen > 0) ? (1.0f / (float)plen) : 0.0f;

    const float4 xv = reinterpret_cast<const float4*>(x + (size_t)warp * DD)[lane];
    float4 xn;
    xn.x = xv.x + num.x * ip;
    xn.y = xv.y + num.y * ip;
    xn.z = xv.z + num.z * ip;
    xn.w = xv.w + num.w * ip;
    reinterpret_cast<float4*>(xout + (size_t)warp * DD)[lane] = xn;

    float s = xn.x * xn.x + xn.y * xn.y + xn.z * xn.z + xn.w * xn.w;
#pragma unroll
    for (int o = 16; o; o >>= 1) s += __shfl_xor_sync(0xffffffffu, s, o);
    if (lane == 0)
        g_rn[warp] = 1.0f / fmaxf(sqrtf(s), EPS_F);
}

// ---------------------------------------------------------------------------
// Kernel 4: per-edge cosine of prompted features -> keep mask (1.0/0.0).
// ---------------------------------------------------------------------------
__global__ void k_edge_prune(const float* __restrict__ xn,
                             const int* __restrict__ ei,
                             float* __restrict__ keep) {
    int warp = (blockIdx.x * blockDim.x + threadIdx.x) >> 5;
    int lane = threadIdx.x & 31;
    if (warp >= EE) return;
    const int r = ei[warp];
    const int c = ei[EE + warp];
    const float4 a = reinterpret_cast<const float4*>(xn + (size_t)r * DD)[lane];
    const float4 b = reinterpret_cast<const float4*>(xn + (size_t)c * DD)[lane];
    float s = a.x * b.x + a.y * b.y + a.z * b.z + a.w * b.w;
#pragma unroll
    for (int o = 16; o; o >>= 1) s += __shfl_xor_sync(0xffffffffu, s, o);
    if (lane == 0) {
        const float cosv = s * g_rn[r] * g_rn[c];
        keep[warp] = (cosv >= PT_THR) ? 1.0f : 0.0f;
    }
}

// ---------------------------------------------------------------------------
// Launch: inputs per metadata order: x, edge_index, p_sim, p_deg, p_other.
// Output layout: x_new [N*D floats] followed by keep_edges [E floats].
// ---------------------------------------------------------------------------
extern "C" void kernel_launch(void* const* d_in, const int* in_sizes, int n_in,
                              void* d_out, int out_size) {
    const float* x  = (const float*)d_in[0];
    const int*   ei = (const int*)d_in[1];
    const float* ps = (const float*)d_in[2];
    const float* pd = (const float*)d_in[3];
    const float* po = (const float*)d_in[4];

    float* xout = (float*)d_out;
    float* keep = xout + (size_t)NN * DD;

    const int TPB = 256;            // 8 warps per block
    const int WPB = TPB / 32;

    const int nblk_nodes = (NN + WPB - 1) / WPB;   // 12500
    const int nblk_edges = (EE + WPB - 1) / WPB;   // 80000

    k_norms<<<nblk_nodes, TPB>>>(x);
    k_edge_scatter<<<nblk_edges, TPB>>>(x, ei);
    k_node<<<nblk_nodes, TPB>>>(x, ps, pd, po, xout);
    k_edge_prune<<<nblk_edges, TPB>>>(xout, ei, keep);
}

// round 3
// speedup vs baseline: 2.3756x; 2.3756x over previous
#include <cuda_runtime.h>

// RobustPrompt_I — restructured:
//   K0 prep   : prompt gram matrix, PP class table, all-nonzero flags (1 warp)
//   K1 pre    : per-node 1/||x||, x·ps, x·pd, x·po  (octet-per-node)
//   K2 edge   : raw dot(x_r,x_c) -> g_dot, scaled cos scatter-add (octet-per-edge)
//   K3 node   : masks -> class, x_new = x + f, rn = 1/max(||x_new||,eps)
//   K4 prune  : cos via algebraic expansion, NO row gathers (thread-per-edge)
//
// cos(x_new_r, x_new_c) numerator = dot(x_r,x_c) + x_r·f_c + x_c·f_r + f_r·f_c
// where f in span{ps,pd,po} with per-node class in {S,D,A,O,Z,SD}. This removes
// the second 655MB gather pass entirely.

#define NN 100000
#define EE 640000
#define DD 128

#define SIM_THR 0.2f
#define DEG_THR 3.0f
#define PT_THR  0.1f
#define EPS_F   1e-8f

// ---- scratch (__device__ globals; no allocation allowed) -------------------
__device__ float  g_inv[NN];    // 1/||x_i||
__device__ float  g_c[NN];      // scatter-accumulated edge cosine per dst
__device__ float  g_deg[NN];    // in-degree (exact in f32)
__device__ float4 g_w[NN];      // (x·ps, x·pd, x·po, rn)  [.w filled by K3]
__device__ unsigned char g_cls[NN]; // prompt class 0..5
__device__ float  g_dot[EE];    // raw dot(x_r, x_c) from pass 2
__device__ float  g_PP[36];     // f_a · f_b per class pair
__device__ int    g_nz[3];      // all-components-nonzero flags for ps,pd,po

// classes: 0=S(ps) 1=D(pd) 2=A((ps+pd)/2) 3=O(po) 4=Z(0) 5=SD(ps+pd)
__constant__ float4 c_coef[6] = {
    {1.f, 0.f, 0.f, 0.f}, {0.f, 1.f, 0.f, 0.f}, {0.5f, 0.5f, 0.f, 0.f},
    {0.f, 0.f, 1.f, 0.f}, {0.f, 0.f, 0.f, 0.f}, {1.f, 1.f, 0.f, 0.f}};

// ---------------------------------------------------------------------------
// K0: one warp. Gram of (ps,pd,po), PP table, nonzero flags.
// ---------------------------------------------------------------------------
__global__ void k_prep(const float* __restrict__ ps,
                       const float* __restrict__ pd,
                       const float* __restrict__ po) {
    const int lane = threadIdx.x;
    float ss = 0.f, sd = 0.f, so = 0.f, dd = 0.f, dpo = 0.f, oo = 0.f;
    bool ns = true, nd = true, no = true;
#pragma unroll
    for (int i = 0; i < 4; i++) {
        const int t = lane + 32 * i;
        const float s = ps[t], d = pd[t], o = po[t];
        ss += s * s; sd += s * d; so += s * o;
        dd += d * d; dpo += d * o; oo += o * o;
        ns &= (s != 0.f); nd &= (d != 0.f); no &= (o != 0.f);
    }
#pragma unroll
    for (int o = 16; o; o >>= 1) {
        ss  += __shfl_xor_sync(0xffffffffu, ss,  o);
        sd  += __shfl_xor_sync(0xffffffffu, sd,  o);
        so  += __shfl_xor_sync(0xffffffffu, so,  o);
        dd  += __shfl_xor_sync(0xffffffffu, dd,  o);
        dpo += __shfl_xor_sync(0xffffffffu, dpo, o);
        oo  += __shfl_xor_sync(0xffffffffu, oo,  o);
    }
    const bool ans = __all_sync(0xffffffffu, ns);
    const bool and_ = __all_sync(0xffffffffu, nd);
    const bool ano = __all_sync(0xffffffffu, no);
    if (lane == 0) {
        g_nz[0] = ans; g_nz[1] = and_; g_nz[2] = ano;
        // G = [[ss,sd,so],[sd,dd,dpo],[so,dpo,oo]]
        for (int a = 0; a < 6; a++) {
            const float4 ca = c_coef[a];
            const float gx = ca.x * ss + ca.y * sd  + ca.z * so;
            const float gy = ca.x * sd + ca.y * dd  + ca.z * dpo;
            const float gz = ca.x * so + ca.y * dpo + ca.z * oo;
            for (int b = 0; b < 6; b++) {
                const float4 cb = c_coef[b];
                g_PP[a * 6 + b] = gx * cb.x + gy * cb.y + gz * cb.z;
            }
        }
    }
}

// ---------------------------------------------------------------------------
// K1: octet-per-node (4 nodes/warp). inv norm + 3 prompt dots; zero scatter.
// ---------------------------------------------------------------------------
__global__ void k_pre(const float* __restrict__ x,
                      const float* __restrict__ ps,
                      const float* __restrict__ pd,
                      const float* __restrict__ po) {
    const int warp = (blockIdx.x * blockDim.x + threadIdx.x) >> 5;
    const int lane = threadIdx.x & 31;
    const int oct  = lane >> 3, ol = lane & 7;
    const int node = warp * 4 + oct;
    if (node >= NN) return;

    const float4* xr = reinterpret_cast<const float4*>(x) + (size_t)node * 32;
    const float4* p4s = reinterpret_cast<const float4*>(ps);
    const float4* p4d = reinterpret_cast<const float4*>(pd);
    const float4* p4o = reinterpret_cast<const float4*>(po);

    float as = 0.f, ad = 0.f, ao = 0.f, ssq = 0.f;
#pragma unroll
    for (int i = 0; i < 4; i++) {
        const int k = i * 8 + ol;
        const float4 v = xr[k];
        const float4 s = p4s[k], d = p4d[k], o = p4o[k];
        as  += v.x * s.x + v.y * s.y + v.z * s.z + v.w * s.w;
        ad  += v.x * d.x + v.y * d.y + v.z * d.z + v.w * d.w;
        ao  += v.x * o.x + v.y * o.y + v.z * o.z + v.w * o.w;
        ssq += v.x * v.x + v.y * v.y + v.z * v.z + v.w * v.w;
    }
#pragma unroll
    for (int o = 4; o; o >>= 1) {
        as  += __shfl_xor_sync(0xffffffffu, as,  o);
        ad  += __shfl_xor_sync(0xffffffffu, ad,  o);
        ao  += __shfl_xor_sync(0xffffffffu, ao,  o);
        ssq += __shfl_xor_sync(0xffffffffu, ssq, o);
    }
    if (ol == 0) {
        g_inv[node] = 1.0f / sqrtf(ssq);
        g_w[node]   = make_float4(as, ad, ao, 0.f);
        g_c[node]   = 0.0f;
        g_deg[node] = 0.0f;
    }
}

// ---------------------------------------------------------------------------
// K2: octet-per-edge (4 edges/warp). raw dot -> g_dot; scaled scatter-add.
// Each LDG.128 fetches 4 full 128B lines (100% sector efficiency).
// ---------------------------------------------------------------------------
__global__ void k_edge_dot(const float* __restrict__ x,
                           const int* __restrict__ ei) {
    const int warp = (blockIdx.x * blockDim.x + threadIdx.x) >> 5;
    const int lane = threadIdx.x & 31;
    const int oct  = lane >> 3, ol = lane & 7;
    const int eid  = warp * 4 + oct;
    if (eid >= EE) return;

    const int r = ei[eid];
    const int c = ei[EE + eid];
    const float4* xr = reinterpret_cast<const float4*>(x) + (size_t)r * 32;
    const float4* xc = reinterpret_cast<const float4*>(x) + (size_t)c * 32;

    float s = 0.f;
#pragma unroll
    for (int i = 0; i < 4; i++) {
        const int k = i * 8 + ol;
        const float4 a = xr[k];
        const float4 b = xc[k];
        s += a.x * b.x + a.y * b.y + a.z * b.z + a.w * b.w;
    }
#pragma unroll
    for (int o = 4; o; o >>= 1) s += __shfl_xor_sync(0xffffffffu, s, o);

    if (ol == 0) {
        g_dot[eid] = s;
        const float e = s * g_inv[r] * g_inv[c];
        atomicAdd(&g_c[c], e);
        atomicAdd(&g_deg[c], 1.0f);
    }
}

// ---------------------------------------------------------------------------
// K3: octet-per-node. masks -> class, x_new = x + f, rn from written values.
// ---------------------------------------------------------------------------
__global__ void k_node(const float* __restrict__ x,
                       const float* __restrict__ ps,
                       const float* __restrict__ pd,
                       const float* __restrict__ po,
                       float* __restrict__ xout) {
    const int warp = (blockIdx.x * blockDim.x + threadIdx.x) >> 5;
    const int lane = threadIdx.x & 31;
    const int oct  = lane >> 3, ol = lane & 7;
    const int node = warp * 4 + oct;
    if (node >= NN) return;

    // all 8 lanes of the octet compute the scalar logic redundantly (broadcast loads)
    const float cacc = g_c[node];
    const float deg  = g_deg[node];
    const bool m_sim = (deg > 0.0f) && (cacc / deg <= SIM_THR); // deg>0 -> max(deg,1)=deg
    const bool m_deg = (deg <= DEG_THR);
    const bool m_oth = !(m_sim || m_deg);
    const int nzs = g_nz[0], nzd = g_nz[1], nzo = g_nz[2];

    // numerator sums ALL masked prompts; plen counts only masked&&all-nonzero
    int cls;
    if (m_oth)               cls = nzo ? 3 : 4;                 // O / Z
    else if (m_sim && m_deg) cls = (nzs + nzd == 2) ? 2 : ((nzs + nzd == 1) ? 5 : 4); // A/SD/Z
    else if (m_sim)          cls = nzs ? 0 : 4;                 // S / Z
    else                     cls = nzd ? 1 : 4;                 // D / Z
    const float4 cf = c_coef[cls];   // (alpha,beta,gamma) for f = a*ps+b*pd+g*po

    const float4* xr  = reinterpret_cast<const float4*>(x) + (size_t)node * 32;
    float4* xw        = reinterpret_cast<float4*>(xout) + (size_t)node * 32;
    const float4* p4s = reinterpret_cast<const float4*>(ps);
    const float4* p4d = reinterpret_cast<const float4*>(pd);
    const float4* p4o = reinterpret_cast<const float4*>(po);

    float ssq = 0.f;
#pragma unroll
    for (int i = 0; i < 4; i++) {
        const int k = i * 8 + ol;
        const float4 v = xr[k];
        const float4 s = p4s[k], d = p4d[k], o = p4o[k];
        float4 f;
        f.x = cf.x * s.x + cf.y * d.x; f.x += cf.z * o.x;
        f.y = cf.x * s.y + cf.y * d.y; f.y += cf.z * o.y;
        f.z = cf.x * s.z + cf.y * d.z; f.z += cf.z * o.z;
        f.w = cf.x * s.w + cf.y * d.w; f.w += cf.z * o.w;
        float4 xn;
        xn.x = v.x + f.x; xn.y = v.y + f.y; xn.z = v.z + f.z; xn.w = v.w + f.w;
        xw[k] = xn;
        ssq += xn.x * xn.x + xn.y * xn.y + xn.z * xn.z + xn.w * xn.w;
    }
#pragma unroll
    for (int o = 4; o; o >>= 1) ssq += __shfl_xor_sync(0xffffffffu, ssq, o);

    if (ol == 0) {
        const float rn = 1.0f / fmaxf(sqrtf(ssq), EPS_F);
        g_w[node].w = rn;
        g_cls[node] = (unsigned char)cls;
    }
}

// ---------------------------------------------------------------------------
// K4: thread-per-edge. cos = (dot + x_r·f_c + x_c·f_r + f_r·f_c) * rn_r * rn_c
// No 512B row gathers — only 16B lookups in a 1.7MB L2-resident table.
// ---------------------------------------------------------------------------
__global__ void k_prune(const int* __restrict__ ei,
                        float* __restrict__ keep) {
    const int e = blockIdx.x * blockDim.x + threadIdx.x;
    if (e >= EE) return;
    const int r = ei[e];
    const int c = ei[EE + e];
    const float4 wr = g_w[r];
    const float4 wc = g_w[c];
    const int cr = g_cls[r];
    const int cc = g_cls[c];
    const float4 fr = c_coef[cr];
    const float4 fc = c_coef[cc];
    float num = g_dot[e];
    num += fc.x * wr.x + fc.y * wr.y + fc.z * wr.z;   // x_r · f_c
    num += fr.x * wc.x + fr.y * wc.y + fr.z * wc.z;   // x_c · f_r
    num += g_PP[cr * 6 + cc];                         // f_r · f_c
    const float cosv = num * wr.w * wc.w;
    keep[e] = (cosv >= PT_THR) ? 1.0f : 0.0f;
}

// ---------------------------------------------------------------------------
extern "C" void kernel_launch(void* const* d_in, const int* in_sizes, int n_in,
                              void* d_out, int out_size) {
    const float* x  = (const float*)d_in[0];
    const int*   ei = (const int*)d_in[1];
    const float* ps = (const float*)d_in[2];
    const float* pd = (const float*)d_in[3];
    const float* po = (const float*)d_in[4];

    float* xout = (float*)d_out;
    float* keep = xout + (size_t)NN * DD;

    const int TPB = 256;
    const int WPB = TPB / 32;                        // 8 warps/block
    const int nodes_per_blk = WPB * 4;               // 32
    const int edges_per_blk = WPB * 4;               // 32 (octet mapping)

    k_prep<<<1, 32>>>(ps, pd, po);
    k_pre<<<(NN + nodes_per_blk - 1) / nodes_per_blk, TPB>>>(x, ps, pd, po);
    k_edge_dot<<<(EE + edges_per_blk - 1) / edges_per_blk, TPB>>>(x, ei);
    k_node<<<(NN + nodes_per_blk - 1) / nodes_per_blk, TPB>>>(x, ps, pd, po, xout);
    k_prune<<<(EE + TPB - 1) / TPB, TPB>>>(ei, keep);
}

// round 5
// speedup vs baseline: 2.4695x; 1.0395x over previous
#include <cuda_runtime.h>

// RobustPrompt_I — 4-launch pipeline:
//   K1 pre   : per-node ssq, 1/||x||, x·ps/pd/po; block0 also builds PP + nz flags
//   K2 edge  : raw dot(x_r,x_c) -> g_dot, cosine scatter-add (octet-per-edge)
//   K3 addf  : class -> xout = x + f (pure stream, NO reduction);
//              rn computed ANALYTICALLY: ||x+f||^2 = ssq + 2(x·f) + ||f||^2
//   K4 prune : cos via algebraic expansion over the L2-resident node table

#define NN 100000
#define EE 640000
#define DD 128

#define SIM_THR 0.2f
#define DEG_THR 3.0f
#define PT_THR  0.1f
#define EPS_F   1e-8f

// ---- scratch (__device__ globals) -----------------------------------------
__device__ float  g_inv[NN];    // 1/||x_i||
__device__ float  g_c[NN];      // scatter-accumulated edge cosine per dst
__device__ float  g_deg[NN];    // in-degree
__device__ float4 g_w[NN];      // (x·ps, x·pd, x·po, ssq) ; .w becomes rn in K3
__device__ unsigned char g_cls[NN];
__device__ float  g_dot[EE];    // raw dot(x_r, x_c)
__device__ float  g_PP[36];     // f_a · f_b per class pair
__device__ int    g_nz[3];      // all-components-nonzero flags for ps,pd,po

// classes: 0=S(ps) 1=D(pd) 2=A((ps+pd)/2) 3=O(po) 4=Z(0) 5=SD(ps+pd)
__constant__ float4 c_coef[6] = {
    {1.f, 0.f, 0.f, 0.f}, {0.f, 1.f, 0.f, 0.f}, {0.5f, 0.5f, 0.f, 0.f},
    {0.f, 0.f, 1.f, 0.f}, {0.f, 0.f, 0.f, 0.f}, {1.f, 1.f, 0.f, 0.f}};

// ---------------------------------------------------------------------------
// K1: octet-per-node (4 nodes/warp). ssq + inv norm + 3 prompt dots; zero
// scatter accumulators. Block 0 / warp 0 additionally builds the prompt gram,
// PP class table and nonzero flags.
// ---------------------------------------------------------------------------
__global__ void k_pre(const float* __restrict__ x,
                      const float* __restrict__ ps,
                      const float* __restrict__ pd,
                      const float* __restrict__ po) {
    // ---- prompt prep (one warp, runs alongside its node work) -------------
    if (blockIdx.x == 0 && threadIdx.x < 32) {
        const int lane = threadIdx.x;
        float ss = 0.f, sd = 0.f, so = 0.f, dd2 = 0.f, dpo = 0.f, oo = 0.f;
        bool ns = true, nd = true, no = true;
#pragma unroll
        for (int i = 0; i < 4; i++) {
            const int t = lane + 32 * i;
            const float s = ps[t], d = pd[t], o = po[t];
            ss += s * s; sd += s * d; so += s * o;
            dd2 += d * d; dpo += d * o; oo += o * o;
            ns &= (s != 0.f); nd &= (d != 0.f); no &= (o != 0.f);
        }
#pragma unroll
        for (int o = 16; o; o >>= 1) {
            ss  += __shfl_xor_sync(0xffffffffu, ss,  o);
            sd  += __shfl_xor_sync(0xffffffffu, sd,  o);
            so  += __shfl_xor_sync(0xffffffffu, so,  o);
            dd2 += __shfl_xor_sync(0xffffffffu, dd2, o);
            dpo += __shfl_xor_sync(0xffffffffu, dpo, o);
            oo  += __shfl_xor_sync(0xffffffffu, oo,  o);
        }
        const bool ans = __all_sync(0xffffffffu, ns);
        const bool and_ = __all_sync(0xffffffffu, nd);
        const bool ano = __all_sync(0xffffffffu, no);
        if (lane == 0) {
            g_nz[0] = ans; g_nz[1] = and_; g_nz[2] = ano;
            for (int a = 0; a < 6; a++) {
                const float4 ca = c_coef[a];
                const float gx = ca.x * ss + ca.y * sd  + ca.z * so;
                const float gy = ca.x * sd + ca.y * dd2 + ca.z * dpo;
                const float gz = ca.x * so + ca.y * dpo + ca.z * oo;
                for (int b = 0; b < 6; b++) {
                    const float4 cb = c_coef[b];
                    g_PP[a * 6 + b] = gx * cb.x + gy * cb.y + gz * cb.z;
                }
            }
        }
    }

    // ---- per-node work ----------------------------------------------------
    const int warp = (blockIdx.x * blockDim.x + threadIdx.x) >> 5;
    const int lane = threadIdx.x & 31;
    const int oct  = lane >> 3, ol = lane & 7;
    const int node = warp * 4 + oct;
    if (node >= NN) return;

    const float4* xr  = reinterpret_cast<const float4*>(x) + (size_t)node * 32;
    const float4* p4s = reinterpret_cast<const float4*>(ps);
    const float4* p4d = reinterpret_cast<const float4*>(pd);
    const float4* p4o = reinterpret_cast<const float4*>(po);

    float as = 0.f, ad = 0.f, ao = 0.f, ssq = 0.f;
#pragma unroll
    for (int i = 0; i < 4; i++) {
        const int k = i * 8 + ol;
        const float4 v = xr[k];
        const float4 s = p4s[k], d = p4d[k], o = p4o[k];
        as  += v.x * s.x + v.y * s.y + v.z * s.z + v.w * s.w;
        ad  += v.x * d.x + v.y * d.y + v.z * d.z + v.w * d.w;
        ao  += v.x * o.x + v.y * o.y + v.z * o.z + v.w * o.w;
        ssq += v.x * v.x + v.y * v.y + v.z * v.z + v.w * v.w;
    }
#pragma unroll
    for (int o = 4; o; o >>= 1) {
        as  += __shfl_xor_sync(0xffffffffu, as,  o);
        ad  += __shfl_xor_sync(0xffffffffu, ad,  o);
        ao  += __shfl_xor_sync(0xffffffffu, ao,  o);
        ssq += __shfl_xor_sync(0xffffffffu, ssq, o);
    }
    if (ol == 0) {
        g_inv[node] = 1.0f / sqrtf(ssq);
        g_w[node]   = make_float4(as, ad, ao, ssq);
        g_c[node]   = 0.0f;
        g_deg[node] = 0.0f;
    }
}

// ---------------------------------------------------------------------------
// K2: octet-per-edge (4 edges/warp). raw dot -> g_dot; scaled scatter-add.
// Each LDG.128 fetches 4 full 128B lines (100% sector efficiency).
// ---------------------------------------------------------------------------
__global__ void k_edge_dot(const float* __restrict__ x,
                           const int* __restrict__ ei) {
    const int warp = (blockIdx.x * blockDim.x + threadIdx.x) >> 5;
    const int lane = threadIdx.x & 31;
    const int oct  = lane >> 3, ol = lane & 7;
    const int eid  = warp * 4 + oct;
    if (eid >= EE) return;

    const int r = ei[eid];
    const int c = ei[EE + eid];
    const float4* xr = reinterpret_cast<const float4*>(x) + (size_t)r * 32;
    const float4* xc = reinterpret_cast<const float4*>(x) + (size_t)c * 32;

    float s = 0.f;
#pragma unroll
    for (int i = 0; i < 4; i++) {
        const int k = i * 8 + ol;
        const float4 a = xr[k];
        const float4 b = xc[k];
        s += a.x * b.x + a.y * b.y + a.z * b.z + a.w * b.w;
    }
#pragma unroll
    for (int o = 4; o; o >>= 1) s += __shfl_xor_sync(0xffffffffu, s, o);

    if (ol == 0) {
        g_dot[eid] = s;
        const float e = s * g_inv[r] * g_inv[c];
        atomicAdd(&g_c[c], e);
        atomicAdd(&g_deg[c], 1.0f);
    }
}

// ---------------------------------------------------------------------------
// K3: octet-per-node pure stream. class -> xout = x + f; rn analytic
// (no reduction: ||x+f||^2 = ssq + 2*cf·w + PP[cls][cls]).
// ---------------------------------------------------------------------------
__global__ void k_addf(const float* __restrict__ x,
                       const float* __restrict__ ps,
                       const float* __restrict__ pd,
                       const float* __restrict__ po,
                       float* __restrict__ xout) {
    const int warp = (blockIdx.x * blockDim.x + threadIdx.x) >> 5;
    const int lane = threadIdx.x & 31;
    const int oct  = lane >> 3, ol = lane & 7;
    const int node = warp * 4 + oct;
    if (node >= NN) return;

    const float cacc = g_c[node];       // broadcast within octet
    const float deg  = g_deg[node];
    const bool m_sim = (deg > 0.0f) && (cacc / deg <= SIM_THR);
    const bool m_deg = (deg <= DEG_THR);
    const bool m_oth = !(m_sim || m_deg);
    const int nzs = g_nz[0], nzd = g_nz[1], nzo = g_nz[2];

    // numerator sums ALL masked prompts; plen counts only masked&&all-nonzero
    int cls;
    if (m_oth)               cls = nzo ? 3 : 4;
    else if (m_sim && m_deg) cls = (nzs + nzd == 2) ? 2 : ((nzs + nzd == 1) ? 5 : 4);
    else if (m_sim)          cls = nzs ? 0 : 4;
    else                     cls = nzd ? 1 : 4;
    const float4 cf = c_coef[cls];

    const float4* xr  = reinterpret_cast<const float4*>(x) + (size_t)node * 32;
    float4* xw        = reinterpret_cast<float4*>(xout) + (size_t)node * 32;
    const float4* p4s = reinterpret_cast<const float4*>(ps);
    const float4* p4d = reinterpret_cast<const float4*>(pd);
    const float4* p4o = reinterpret_cast<const float4*>(po);

#pragma unroll
    for (int i = 0; i < 4; i++) {
        const int k = i * 8 + ol;
        const float4 v = xr[k];
        const float4 s = p4s[k], d = p4d[k], o = p4o[k];
        float4 xn;
        // same FMA order as validated in R3 (cf.x*s + cf.y*d, then + cf.z*o)
        float fx = cf.x * s.x + cf.y * d.x; fx += cf.z * o.x;
        float fy = cf.x * s.y + cf.y * d.y; fy += cf.z * o.y;
        float fz = cf.x * s.z + cf.y * d.z; fz += cf.z * o.z;
        float fw = cf.x * s.w + cf.y * d.w; fw += cf.z * o.w;
        xn.x = v.x + fx; xn.y = v.y + fy; xn.z = v.z + fz; xn.w = v.w + fw;
        xw[k] = xn;
    }

    if (ol == 0) {
        const float4 w = g_w[node];                       // (as, ad, ao, ssq)
        const float xf = cf.x * w.x + cf.y * w.y + cf.z * w.z;   // x·f
        float nsq = w.w + 2.0f * xf + g_PP[cls * 6 + cls];       // ||x+f||^2
        nsq = fmaxf(nsq, 0.0f);
        const float rn = 1.0f / fmaxf(sqrtf(nsq), EPS_F);
        g_w[node].w = rn;                                 // overwrite ssq with rn
        g_cls[node] = (unsigned char)cls;
    }
}

// ---------------------------------------------------------------------------
// K4: thread-per-edge. cos = (dot + x_r·f_c + x_c·f_r + f_r·f_c) * rn_r * rn_c
// ---------------------------------------------------------------------------
__global__ void k_prune(const int* __restrict__ ei,
                        float* __restrict__ keep) {
    const int e = blockIdx.x * blockDim.x + threadIdx.x;
    if (e >= EE) return;
    const int r = ei[e];
    const int c = ei[EE + e];
    const float4 wr = g_w[r];
    const float4 wc = g_w[c];
    const int cr = g_cls[r];
    const int cc = g_cls[c];
    const float4 fr = c_coef[cr];
    const float4 fc = c_coef[cc];
    float num = g_dot[e];
    num += fc.x * wr.x + fc.y * wr.y + fc.z * wr.z;   // x_r · f_c
    num += fr.x * wc.x + fr.y * wc.y + fr.z * wc.z;   // x_c · f_r
    num += g_PP[cr * 6 + cc];                         // f_r · f_c
    const float cosv = num * wr.w * wc.w;
    keep[e] = (cosv >= PT_THR) ? 1.0f : 0.0f;
}

// ---------------------------------------------------------------------------
extern "C" void kernel_launch(void* const* d_in, const int* in_sizes, int n_in,
                              void* d_out, int out_size) {
    const float* x  = (const float*)d_in[0];
    const int*   ei = (const int*)d_in[1];
    const float* ps = (const float*)d_in[2];
    const float* pd = (const float*)d_in[3];
    const float* po = (const float*)d_in[4];

    float* xout = (float*)d_out;
    float* keep = xout + (size_t)NN * DD;

    const int TPB = 256;
    const int per_blk = (TPB / 32) * 4;   // 32 nodes or edges per block

    k_pre<<<(NN + per_blk - 1) / per_blk, TPB>>>(x, ps, pd, po);
    k_edge_dot<<<(EE + per_blk - 1) / per_blk, TPB>>>(x, ei);
    k_addf<<<(NN + per_blk - 1) / per_blk, TPB>>>(x, ps, pd, po, xout);
    k_prune<<<(EE + TPB - 1) / TPB, TPB>>>(ei, keep);
}

// round 7
// speedup vs baseline: 2.4809x; 1.0046x over previous
#include <cuda_runtime.h>

// RobustPrompt_I — 4-launch pipeline:
//   K1 pre   : per-node ssq, 1/||x||, x·ps/pd/po; block0 builds gram G + nz flags
//   K2 edge  : raw dot(x_r,x_c) -> g_dot, cosine scatter-add (octet-per-edge)
//   K3 addf  : class -> xout = x + f (pure stream); writes 32B node record
//              (p = w + 0.5*G*cf, cf, rn) with rn analytic from ||x+f||^2
//   K4 prune : cos = (dot + cf_c·p_r + cf_r·p_c) * rn_r * rn_c  — flat gathers,
//              no dependent class/PP lookups, 2 edges per thread for MLP

#define NN 100000
#define EE 640000
#define DD 128

#define SIM_THR 0.2f
#define DEG_THR 3.0f
#define PT_THR  0.1f
#define EPS_F   1e-8f

// ---- scratch (__device__ globals) -----------------------------------------
__device__ float  g_inv[NN];     // 1/||x_i||
__device__ float  g_c[NN];       // scatter-accumulated edge cosine per dst
__device__ float  g_deg[NN];     // in-degree
__device__ float4 g_w[NN];       // (x·ps, x·pd, x·po, ssq)
__device__ float4 g_nr[2 * NN];  // node record: [2i]=(p0,p1,p2,rn) [2i+1]=(cf0,cf1,cf2,0)
__device__ float  g_dot[EE];     // raw dot(x_r, x_c)
__device__ float  g_G[6];        // gram packed: ss, sd, so, dd, dpo, oo
__device__ int    g_nz[3];       // all-components-nonzero flags for ps,pd,po

// classes: 0=S(ps) 1=D(pd) 2=A((ps+pd)/2) 3=O(po) 4=Z(0) 5=SD(ps+pd)
__constant__ float4 c_coef[6] = {
    {1.f, 0.f, 0.f, 0.f}, {0.f, 1.f, 0.f, 0.f}, {0.5f, 0.5f, 0.f, 0.f},
    {0.f, 0.f, 1.f, 0.f}, {0.f, 0.f, 0.f, 0.f}, {1.f, 1.f, 0.f, 0.f}};

// ---------------------------------------------------------------------------
// K1: octet-per-node (4 nodes/warp). ssq + inv norm + 3 prompt dots; zero
// scatter accumulators. Block 0 / warp 0 additionally builds gram + nz flags.
// ---------------------------------------------------------------------------
__global__ void k_pre(const float* __restrict__ x,
                      const float* __restrict__ ps,
                      const float* __restrict__ pd,
                      const float* __restrict__ po) {
    if (blockIdx.x == 0 && threadIdx.x < 32) {
        const int lane = threadIdx.x;
        float ss = 0.f, sd = 0.f, so = 0.f, dd2 = 0.f, dpo = 0.f, oo = 0.f;
        bool ns = true, nd = true, no = true;
#pragma unroll
        for (int i = 0; i < 4; i++) {
            const int t = lane + 32 * i;
            const float s = ps[t], d = pd[t], o = po[t];
            ss += s * s; sd += s * d; so += s * o;
            dd2 += d * d; dpo += d * o; oo += o * o;
            ns &= (s != 0.f); nd &= (d != 0.f); no &= (o != 0.f);
        }
#pragma unroll
        for (int o = 16; o; o >>= 1) {
            ss  += __shfl_xor_sync(0xffffffffu, ss,  o);
            sd  += __shfl_xor_sync(0xffffffffu, sd,  o);
            so  += __shfl_xor_sync(0xffffffffu, so,  o);
            dd2 += __shfl_xor_sync(0xffffffffu, dd2, o);
            dpo += __shfl_xor_sync(0xffffffffu, dpo, o);
            oo  += __shfl_xor_sync(0xffffffffu, oo,  o);
        }
        const bool ans = __all_sync(0xffffffffu, ns);
        const bool and_ = __all_sync(0xffffffffu, nd);
        const bool ano = __all_sync(0xffffffffu, no);
        if (lane == 0) {
            g_nz[0] = ans; g_nz[1] = and_; g_nz[2] = ano;
            g_G[0] = ss; g_G[1] = sd; g_G[2] = so;
            g_G[3] = dd2; g_G[4] = dpo; g_G[5] = oo;
        }
    }

    const int warp = (blockIdx.x * blockDim.x + threadIdx.x) >> 5;
    const int lane = threadIdx.x & 31;
    const int oct  = lane >> 3, ol = lane & 7;
    const int node = warp * 4 + oct;
    if (node >= NN) return;

    const float4* xr  = reinterpret_cast<const float4*>(x) + (size_t)node * 32;
    const float4* p4s = reinterpret_cast<const float4*>(ps);
    const float4* p4d = reinterpret_cast<const float4*>(pd);
    const float4* p4o = reinterpret_cast<const float4*>(po);

    // batch the x loads up front for MLP
    float4 v0 = xr[ol], v1 = xr[8 + ol], v2 = xr[16 + ol], v3 = xr[24 + ol];
    float as = 0.f, ad = 0.f, ao = 0.f, ssq = 0.f;
    const float4 vv[4] = {v0, v1, v2, v3};
#pragma unroll
    for (int i = 0; i < 4; i++) {
        const int k = i * 8 + ol;
        const float4 v = vv[i];
        const float4 s = p4s[k], d = p4d[k], o = p4o[k];
        as  += v.x * s.x + v.y * s.y + v.z * s.z + v.w * s.w;
        ad  += v.x * d.x + v.y * d.y + v.z * d.z + v.w * d.w;
        ao  += v.x * o.x + v.y * o.y + v.z * o.z + v.w * o.w;
        ssq += v.x * v.x + v.y * v.y + v.z * v.z + v.w * v.w;
    }
#pragma unroll
    for (int o = 4; o; o >>= 1) {
        as  += __shfl_xor_sync(0xffffffffu, as,  o);
        ad  += __shfl_xor_sync(0xffffffffu, ad,  o);
        ao  += __shfl_xor_sync(0xffffffffu, ao,  o);
        ssq += __shfl_xor_sync(0xffffffffu, ssq, o);
    }
    if (ol == 0) {
        g_inv[node] = 1.0f / sqrtf(ssq);
        g_w[node]   = make_float4(as, ad, ao, ssq);
        g_c[node]   = 0.0f;
        g_deg[node] = 0.0f;
    }
}

// ---------------------------------------------------------------------------
// K2: octet-per-edge (4 edges/warp). raw dot -> g_dot; scaled scatter-add.
// ---------------------------------------------------------------------------
__global__ void k_edge_dot(const float* __restrict__ x,
                           const int* __restrict__ ei) {
    const int warp = (blockIdx.x * blockDim.x + threadIdx.x) >> 5;
    const int lane = threadIdx.x & 31;
    const int oct  = lane >> 3, ol = lane & 7;
    const int eid  = warp * 4 + oct;
    if (eid >= EE) return;

    const int r = ei[eid];
    const int c = ei[EE + eid];
    const float4* xr = reinterpret_cast<const float4*>(x) + (size_t)r * 32;
    const float4* xc = reinterpret_cast<const float4*>(x) + (size_t)c * 32;

    float s = 0.f;
#pragma unroll
    for (int i = 0; i < 4; i++) {
        const int k = i * 8 + ol;
        const float4 a = xr[k];
        const float4 b = xc[k];
        s += a.x * b.x + a.y * b.y + a.z * b.z + a.w * b.w;
    }
#pragma unroll
    for (int o = 4; o; o >>= 1) s += __shfl_xor_sync(0xffffffffu, s, o);

    if (ol == 0) {
        g_dot[eid] = s;
        const float e = s * g_inv[r] * g_inv[c];
        atomicAdd(&g_c[c], e);
        atomicAdd(&g_deg[c], 1.0f);
    }
}

// ---------------------------------------------------------------------------
// K3: octet-per-node pure stream. class -> xout = x + f; writes node record
// (p = w + 0.5*G*cf, cf, rn) with rn analytic.
// ---------------------------------------------------------------------------
__global__ void k_addf(const float* __restrict__ x,
                       const float* __restrict__ ps,
                       const float* __restrict__ pd,
                       const float* __restrict__ po,
                       float* __restrict__ xout) {
    const int warp = (blockIdx.x * blockDim.x + threadIdx.x) >> 5;
    const int lane = threadIdx.x & 31;
    const int oct  = lane >> 3, ol = lane & 7;
    const int node = warp * 4 + oct;
    if (node >= NN) return;

    const float cacc = g_c[node];
    const float deg  = g_deg[node];
    const bool m_sim = (deg > 0.0f) && (cacc / deg <= SIM_THR);
    const bool m_deg = (deg <= DEG_THR);
    const bool m_oth = !(m_sim || m_deg);
    const int nzs = g_nz[0], nzd = g_nz[1], nzo = g_nz[2];

    // numerator sums ALL masked prompts; plen counts only masked&&all-nonzero
    int cls;
    if (m_oth)               cls = nzo ? 3 : 4;
    else if (m_sim && m_deg) cls = (nzs + nzd == 2) ? 2 : ((nzs + nzd == 1) ? 5 : 4);
    else if (m_sim)          cls = nzs ? 0 : 4;
    else                     cls = nzd ? 1 : 4;
    const float4 cf = c_coef[cls];

    const float4* xr  = reinterpret_cast<const float4*>(x) + (size_t)node * 32;
    float4* xw        = reinterpret_cast<float4*>(xout) + (size_t)node * 32;
    const float4* p4s = reinterpret_cast<const float4*>(ps);
    const float4* p4d = reinterpret_cast<const float4*>(pd);
    const float4* p4o = reinterpret_cast<const float4*>(po);

#pragma unroll
    for (int i = 0; i < 4; i++) {
        const int k = i * 8 + ol;
        const float4 v = xr[k];
        const float4 s = p4s[k], d = p4d[k], o = p4o[k];
        float4 xn;
        float fx = cf.x * s.x + cf.y * d.x; fx += cf.z * o.x;
        float fy = cf.x * s.y + cf.y * d.y; fy += cf.z * o.y;
        float fz = cf.x * s.z + cf.y * d.z; fz += cf.z * o.z;
        float fw = cf.x * s.w + cf.y * d.w; fw += cf.z * o.w;
        xn.x = v.x + fx; xn.y = v.y + fy; xn.z = v.z + fz; xn.w = v.w + fw;
        xw[k] = xn;
    }

    if (ol == 0) {
        const float4 w = g_w[node];                      // (as, ad, ao, ssq)
        // G·cf (3x3 symmetric gram packed ss,sd,so,dd,dpo,oo)
        const float gv0 = g_G[0] * cf.x + g_G[1] * cf.y + g_G[2] * cf.z;
        const float gv1 = g_G[1] * cf.x + g_G[3] * cf.y + g_G[4] * cf.z;
        const float gv2 = g_G[2] * cf.x + g_G[4] * cf.y + g_G[5] * cf.z;
        const float xf    = cf.x * w.x + cf.y * w.y + cf.z * w.z;   // x·f
        const float pself = cf.x * gv0 + cf.y * gv1 + cf.z * gv2;   // ||f||^2
        float nsq = w.w + 2.0f * xf + pself;
        nsq = fmaxf(nsq, 0.0f);
        const float rn = 1.0f / fmaxf(sqrtf(nsq), EPS_F);
        g_nr[2 * node]     = make_float4(w.x + 0.5f * gv0,
                                         w.y + 0.5f * gv1,
                                         w.z + 0.5f * gv2, rn);
        g_nr[2 * node + 1] = make_float4(cf.x, cf.y, cf.z, 0.f);
    }
}

// ---------------------------------------------------------------------------
// K4: 2 edges per thread (both coalesced). Flat 32B record gathers, pure FMA:
//   num = dot + cf_c·p_r + cf_r·p_c ;  cos = num * rn_r * rn_c
// ---------------------------------------------------------------------------
__global__ void k_prune(const int* __restrict__ ei,
                        float* __restrict__ keep) {
    const int base = blockIdx.x * 512 + threadIdx.x;
    const int e0 = base;
    const int e1 = base + 256;

    const int r0 = ei[e0],      c0 = ei[EE + e0];
    const int r1 = (e1 < EE) ? ei[e1] : 0;
    const int c1 = (e1 < EE) ? ei[EE + e1] : 0;

    // 8 independent 16B gathers (pairs share a 32B sector)
    const float4 ar0 = g_nr[2 * r0],     br0 = g_nr[2 * r0 + 1];
    const float4 ac0 = g_nr[2 * c0],     bc0 = g_nr[2 * c0 + 1];
    const float4 ar1 = g_nr[2 * r1],     br1 = g_nr[2 * r1 + 1];
    const float4 ac1 = g_nr[2 * c1],     bc1 = g_nr[2 * c1 + 1];

    const float d0 = g_dot[e0];
    const float d1 = (e1 < EE) ? g_dot[e1] : 0.f;

    float n0 = d0;
    n0 += bc0.x * ar0.x + bc0.y * ar0.y + bc0.z * ar0.z;   // cf_c · p_r
    n0 += br0.x * ac0.x + br0.y * ac0.y + br0.z * ac0.z;   // cf_r · p_c
    keep[e0] = (n0 * ar0.w * ac0.w >= PT_THR) ? 1.0f : 0.0f;

    if (e1 < EE) {
        float n1 = d1;
        n1 += bc1.x * ar1.x + bc1.y * ar1.y + bc1.z * ar1.z;
        n1 += br1.x * ac1.x + br1.y * ac1.y + br1.z * ac1.z;
        keep[e1] = (n1 * ar1.w * ac1.w >= PT_THR) ? 1.0f : 0.0f;
    }
}

// ---------------------------------------------------------------------------
extern "C" void kernel_launch(void* const* d_in, const int* in_sizes, int n_in,
                              void* d_out, int out_size) {
    const float* x  = (const float*)d_in[0];
    const int*   ei = (const int*)d_in[1];
    const float* ps = (const float*)d_in[2];
    const float* pd = (const float*)d_in[3];
    const float* po = (const float*)d_in[4];

    float* xout = (float*)d_out;
    float* keep = xout + (size_t)NN * DD;

    const int TPB = 256;
    const int per_blk = (TPB / 32) * 4;   // 32 nodes or edges per block

    k_pre<<<(NN + per_blk - 1) / per_blk, TPB>>>(x, ps, pd, po);
    k_edge_dot<<<(EE + per_blk - 1) / per_blk, TPB>>>(x, ei);
    k_addf<<<(NN + per_blk - 1) / per_blk, TPB>>>(x, ps, pd, po, xout);
    k_prune<<<(EE + 511) / 512, TPB>>>(ei, keep);
}

// round 8
// speedup vs baseline: 2.5320x; 1.0206x over previous
#include <cuda_runtime.h>

// RobustPrompt_I — 4-launch pipeline:
//   K1 pre   : per-node ssq, 1/||x||, x·ps/pd/po; block0 builds gram G + nz flags
//   K2 edge  : raw dot(x_r,x_c) -> g_dot, cosine scatter-add (octet-per-edge)
//   K3 addf  : class -> xout = x + f (pure stream); writes ONE 16B node record
//              (p = w + 0.5*G*cf, rn with cls packed in 3 LSBs of mantissa)
//   K4 prune : cos = (dot + cf_c·p_r + cf_r·p_c) * rn_r * rn_c
//              one float4 gather per endpoint (halved L1tex wavefronts)

#define NN 100000
#define EE 640000
#define DD 128

#define SIM_THR 0.2f
#define DEG_THR 3.0f
#define PT_THR  0.1f
#define EPS_F   1e-8f

// ---- scratch (__device__ globals) -----------------------------------------
__device__ float  g_inv[NN];    // 1/||x_i||
__device__ float  g_c[NN];      // scatter-accumulated edge cosine per dst
__device__ float  g_deg[NN];    // in-degree
__device__ float4 g_w[NN];      // (x·ps, x·pd, x·po, ssq)
__device__ float4 g_rec[NN];    // node record: (p0, p1, p2, rn-with-cls-bits)
__device__ float  g_dot[EE];    // raw dot(x_r, x_c)
__device__ float  g_G[6];       // gram packed: ss, sd, so, dd, dpo, oo
__device__ int    g_nz[3];      // all-components-nonzero flags for ps,pd,po

// classes: 0=S(ps) 1=D(pd) 2=A((ps+pd)/2) 3=O(po) 4=Z(0) 5=SD(ps+pd)
__constant__ float4 c_coef[6] = {
    {1.f, 0.f, 0.f, 0.f}, {0.f, 1.f, 0.f, 0.f}, {0.5f, 0.5f, 0.f, 0.f},
    {0.f, 0.f, 1.f, 0.f}, {0.f, 0.f, 0.f, 0.f}, {1.f, 1.f, 0.f, 0.f}};

// ---------------------------------------------------------------------------
// K1: octet-per-node (4 nodes/warp). ssq + inv norm + 3 prompt dots; zero
// scatter accumulators. Block 0 / warp 0 additionally builds gram + nz flags.
// ---------------------------------------------------------------------------
__global__ void k_pre(const float* __restrict__ x,
                      const float* __restrict__ ps,
                      const float* __restrict__ pd,
                      const float* __restrict__ po) {
    if (blockIdx.x == 0 && threadIdx.x < 32) {
        const int lane = threadIdx.x;
        float ss = 0.f, sd = 0.f, so = 0.f, dd2 = 0.f, dpo = 0.f, oo = 0.f;
        bool ns = true, nd = true, no = true;
#pragma unroll
        for (int i = 0; i < 4; i++) {
            const int t = lane + 32 * i;
            const float s = ps[t], d = pd[t], o = po[t];
            ss += s * s; sd += s * d; so += s * o;
            dd2 += d * d; dpo += d * o; oo += o * o;
            ns &= (s != 0.f); nd &= (d != 0.f); no &= (o != 0.f);
        }
#pragma unroll
        for (int o = 16; o; o >>= 1) {
            ss  += __shfl_xor_sync(0xffffffffu, ss,  o);
            sd  += __shfl_xor_sync(0xffffffffu, sd,  o);
            so  += __shfl_xor_sync(0xffffffffu, so,  o);
            dd2 += __shfl_xor_sync(0xffffffffu, dd2, o);
            dpo += __shfl_xor_sync(0xffffffffu, dpo, o);
            oo  += __shfl_xor_sync(0xffffffffu, oo,  o);
        }
        const bool ans = __all_sync(0xffffffffu, ns);
        const bool and_ = __all_sync(0xffffffffu, nd);
        const bool ano = __all_sync(0xffffffffu, no);
        if (lane == 0) {
            g_nz[0] = ans; g_nz[1] = and_; g_nz[2] = ano;
            g_G[0] = ss; g_G[1] = sd; g_G[2] = so;
            g_G[3] = dd2; g_G[4] = dpo; g_G[5] = oo;
        }
    }

    const int warp = (blockIdx.x * blockDim.x + threadIdx.x) >> 5;
    const int lane = threadIdx.x & 31;
    const int oct  = lane >> 3, ol = lane & 7;
    const int node = warp * 4 + oct;
    if (node >= NN) return;

    const float4* xr  = reinterpret_cast<const float4*>(x) + (size_t)node * 32;
    const float4* p4s = reinterpret_cast<const float4*>(ps);
    const float4* p4d = reinterpret_cast<const float4*>(pd);
    const float4* p4o = reinterpret_cast<const float4*>(po);

    // batch the x loads up front for MLP
    float4 v0 = xr[ol], v1 = xr[8 + ol], v2 = xr[16 + ol], v3 = xr[24 + ol];
    float as = 0.f, ad = 0.f, ao = 0.f, ssq = 0.f;
    const float4 vv[4] = {v0, v1, v2, v3};
#pragma unroll
    for (int i = 0; i < 4; i++) {
        const int k = i * 8 + ol;
        const float4 v = vv[i];
        const float4 s = p4s[k], d = p4d[k], o = p4o[k];
        as  += v.x * s.x + v.y * s.y + v.z * s.z + v.w * s.w;
        ad  += v.x * d.x + v.y * d.y + v.z * d.z + v.w * d.w;
        ao  += v.x * o.x + v.y * o.y + v.z * o.z + v.w * o.w;
        ssq += v.x * v.x + v.y * v.y + v.z * v.z + v.w * v.w;
    }
#pragma unroll
    for (int o = 4; o; o >>= 1) {
        as  += __shfl_xor_sync(0xffffffffu, as,  o);
        ad  += __shfl_xor_sync(0xffffffffu, ad,  o);
        ao  += __shfl_xor_sync(0xffffffffu, ao,  o);
        ssq += __shfl_xor_sync(0xffffffffu, ssq, o);
    }
    if (ol == 0) {
        g_inv[node] = 1.0f / sqrtf(ssq);
        g_w[node]   = make_float4(as, ad, ao, ssq);
        g_c[node]   = 0.0f;
        g_deg[node] = 0.0f;
    }
}

// ---------------------------------------------------------------------------
// K2: octet-per-edge (4 edges/warp). raw dot -> g_dot; scaled scatter-add.
// ---------------------------------------------------------------------------
__global__ void k_edge_dot(const float* __restrict__ x,
                           const int* __restrict__ ei) {
    const int warp = (blockIdx.x * blockDim.x + threadIdx.x) >> 5;
    const int lane = threadIdx.x & 31;
    const int oct  = lane >> 3, ol = lane & 7;
    const int eid  = warp * 4 + oct;
    if (eid >= EE) return;

    const int r = ei[eid];
    const int c = ei[EE + eid];
    const float4* xr = reinterpret_cast<const float4*>(x) + (size_t)r * 32;
    const float4* xc = reinterpret_cast<const float4*>(x) + (size_t)c * 32;

    float s = 0.f;
#pragma unroll
    for (int i = 0; i < 4; i++) {
        const int k = i * 8 + ol;
        const float4 a = xr[k];
        const float4 b = xc[k];
        s += a.x * b.x + a.y * b.y + a.z * b.z + a.w * b.w;
    }
#pragma unroll
    for (int o = 4; o; o >>= 1) s += __shfl_xor_sync(0xffffffffu, s, o);

    if (ol == 0) {
        g_dot[eid] = s;
        const float e = s * g_inv[r] * g_inv[c];
        atomicAdd(&g_c[c], e);
        atomicAdd(&g_deg[c], 1.0f);
    }
}

// ---------------------------------------------------------------------------
// K3: octet-per-node pure stream. class -> xout = x + f; writes 16B record
// (p = w + 0.5*G*cf, rn analytic with cls packed in rn's 3 LSBs).
// ---------------------------------------------------------------------------
__global__ void k_addf(const float* __restrict__ x,
                       const float* __restrict__ ps,
                       const float* __restrict__ pd,
                       const float* __restrict__ po,
                       float* __restrict__ xout) {
    const int warp = (blockIdx.x * blockDim.x + threadIdx.x) >> 5;
    const int lane = threadIdx.x & 31;
    const int oct  = lane >> 3, ol = lane & 7;
    const int node = warp * 4 + oct;
    if (node >= NN) return;

    const float cacc = g_c[node];
    const float deg  = g_deg[node];
    const bool m_sim = (deg > 0.0f) && (cacc / deg <= SIM_THR);
    const bool m_deg = (deg <= DEG_THR);
    const bool m_oth = !(m_sim || m_deg);
    const int nzs = g_nz[0], nzd = g_nz[1], nzo = g_nz[2];

    // numerator sums ALL masked prompts; plen counts only masked&&all-nonzero
    int cls;
    if (m_oth)               cls = nzo ? 3 : 4;
    else if (m_sim && m_deg) cls = (nzs + nzd == 2) ? 2 : ((nzs + nzd == 1) ? 5 : 4);
    else if (m_sim)          cls = nzs ? 0 : 4;
    else                     cls = nzd ? 1 : 4;
    const float4 cf = c_coef[cls];

    const float4* xr  = reinterpret_cast<const float4*>(x) + (size_t)node * 32;
    float4* xw        = reinterpret_cast<float4*>(xout) + (size_t)node * 32;
    const float4* p4s = reinterpret_cast<const float4*>(ps);
    const float4* p4d = reinterpret_cast<const float4*>(pd);
    const float4* p4o = reinterpret_cast<const float4*>(po);

#pragma unroll
    for (int i = 0; i < 4; i++) {
        const int k = i * 8 + ol;
        const float4 v = xr[k];
        const float4 s = p4s[k], d = p4d[k], o = p4o[k];
        float4 xn;
        float fx = cf.x * s.x + cf.y * d.x; fx += cf.z * o.x;
        float fy = cf.x * s.y + cf.y * d.y; fy += cf.z * o.y;
        float fz = cf.x * s.z + cf.y * d.z; fz += cf.z * o.z;
        float fw = cf.x * s.w + cf.y * d.w; fw += cf.z * o.w;
        xn.x = v.x + fx; xn.y = v.y + fy; xn.z = v.z + fz; xn.w = v.w + fw;
        xw[k] = xn;
    }

    if (ol == 0) {
        const float4 w = g_w[node];                      // (as, ad, ao, ssq)
        // G·cf (3x3 symmetric gram packed ss,sd,so,dd,dpo,oo)
        const float gv0 = g_G[0] * cf.x + g_G[1] * cf.y + g_G[2] * cf.z;
        const float gv1 = g_G[1] * cf.x + g_G[3] * cf.y + g_G[4] * cf.z;
        const float gv2 = g_G[2] * cf.x + g_G[4] * cf.y + g_G[5] * cf.z;
        const float xf    = cf.x * w.x + cf.y * w.y + cf.z * w.z;   // x·f
        const float pself = cf.x * gv0 + cf.y * gv1 + cf.z * gv2;   // ||f||^2
        float nsq = w.w + 2.0f * xf + pself;
        nsq = fmaxf(nsq, 0.0f);
        const float rn = 1.0f / fmaxf(sqrtf(nsq), EPS_F);
        // pack cls into the 3 LSBs of rn's mantissa (<= 2^-21 rel perturbation)
        const unsigned rbits = (__float_as_uint(rn) & ~7u) | (unsigned)cls;
        g_rec[node] = make_float4(w.x + 0.5f * gv0,
                                  w.y + 0.5f * gv1,
                                  w.z + 0.5f * gv2,
                                  __uint_as_float(rbits));
    }
}

// ---------------------------------------------------------------------------
// K4: 2 edges per thread, ONE float4 gather per endpoint.
//   cls decoded from rn bits; num = dot + cf_c·p_r + cf_r·p_c
//   EE = 512*1250 exactly -> no bounds checks.
// ---------------------------------------------------------------------------
__global__ void k_prune(const int* __restrict__ ei,
                        float* __restrict__ keep) {
    const int base = blockIdx.x * 512 + threadIdx.x;
    const int e0 = base;
    const int e1 = base + 256;

    const int r0 = ei[e0], c0 = ei[EE + e0];
    const int r1 = ei[e1], c1 = ei[EE + e1];

    // 4 independent 16B gathers
    const float4 wr0 = g_rec[r0];
    const float4 wc0 = g_rec[c0];
    const float4 wr1 = g_rec[r1];
    const float4 wc1 = g_rec[c1];

    const float d0 = g_dot[e0];
    const float d1 = g_dot[e1];

    const float4 fr0 = c_coef[__float_as_uint(wr0.w) & 7u];
    const float4 fc0 = c_coef[__float_as_uint(wc0.w) & 7u];
    const float4 fr1 = c_coef[__float_as_uint(wr1.w) & 7u];
    const float4 fc1 = c_coef[__float_as_uint(wc1.w) & 7u];

    float n0 = d0;
    n0 += fc0.x * wr0.x + fc0.y * wr0.y + fc0.z * wr0.z;   // cf_c · p_r
    n0 += fr0.x * wc0.x + fr0.y * wc0.y + fr0.z * wc0.z;   // cf_r · p_c
    keep[e0] = (n0 * wr0.w * wc0.w >= PT_THR) ? 1.0f : 0.0f;

    float n1 = d1;
    n1 += fc1.x * wr1.x + fc1.y * wr1.y + fc1.z * wr1.z;
    n1 += fr1.x * wc1.x + fr1.y * wc1.y + fr1.z * wc1.z;
    keep[e1] = (n1 * wr1.w * wc1.w >= PT_THR) ? 1.0f : 0.0f;
}

// ---------------------------------------------------------------------------
extern "C" void kernel_launch(void* const* d_in, const int* in_sizes, int n_in,
                              void* d_out, int out_size) {
    const float* x  = (const float*)d_in[0];
    const int*   ei = (const int*)d_in[1];
    const float* ps = (const float*)d_in[2];
    const float* pd = (const float*)d_in[3];
    const float* po = (const float*)d_in[4];

    float* xout = (float*)d_out;
    float* keep = xout + (size_t)NN * DD;

    const int TPB = 256;
    const int per_blk = (TPB / 32) * 4;   // 32 nodes or edges per block

    k_pre<<<(NN + per_blk - 1) / per_blk, TPB>>>(x, ps, pd, po);
    k_edge_dot<<<(EE + per_blk - 1) / per_blk, TPB>>>(x, ei);
    k_addf<<<(NN + per_blk - 1) / per_blk, TPB>>>(x, ps, pd, po, xout);
    k_prune<<<EE / 512, TPB>>>(ei, keep);
}

// round 9
// speedup vs baseline: 3.0365x; 1.1992x over previous
#include <cuda_runtime.h>

// RobustPrompt_I — 4-launch pipeline (k_pre eliminated):
//   K0 init  : zero g_c/g_deg; block0 builds prompt gram G + nz flags
//   K1 edge  : per-edge norms computed INLINE from the gathered rows;
//              raw dot -> g_dot, cosine scatter-add (octet-per-edge)
//   K2 addf  : class -> xout = x + f; prompt dots + exact ||x_new||^2
//              accumulated in the same stream loop; writes 16B node record
//   K3 prune : cos from flat records, 4 edges/thread

#define NN 100000
#define EE 640000
#define DD 128

#define SIM_THR 0.2f
#define DEG_THR 3.0f
#define PT_THR  0.1f
#define EPS_F   1e-8f

// ---- scratch (__device__ globals) -----------------------------------------
__device__ float  g_c[NN];      // scatter-accumulated edge cosine per dst
__device__ float  g_deg[NN];    // in-degree
__device__ float4 g_rec[NN];    // node record: (p0, p1, p2, rn-with-cls-bits)
__device__ float  g_dot[EE];    // raw dot(x_r, x_c)
__device__ float  g_G[6];       // gram packed: ss, sd, so, dd, dpo, oo
__device__ int    g_nz[3];      // all-components-nonzero flags for ps,pd,po

// classes: 0=S(ps) 1=D(pd) 2=A((ps+pd)/2) 3=O(po) 4=Z(0) 5=SD(ps+pd)
__constant__ float4 c_coef[6] = {
    {1.f, 0.f, 0.f, 0.f}, {0.f, 1.f, 0.f, 0.f}, {0.5f, 0.5f, 0.f, 0.f},
    {0.f, 0.f, 1.f, 0.f}, {0.f, 0.f, 0.f, 0.f}, {1.f, 1.f, 0.f, 0.f}};

// ---------------------------------------------------------------------------
// K0: zero scatter accumulators; block0/warp0 builds gram + nz flags.
// ---------------------------------------------------------------------------
__global__ void k_init(const float* __restrict__ ps,
                       const float* __restrict__ pd,
                       const float* __restrict__ po) {
    if (blockIdx.x == 0 && threadIdx.x < 32) {
        const int lane = threadIdx.x;
        float ss = 0.f, sd = 0.f, so = 0.f, dd2 = 0.f, dpo = 0.f, oo = 0.f;
        bool ns = true, nd = true, no = true;
#pragma unroll
        for (int i = 0; i < 4; i++) {
            const int t = lane + 32 * i;
            const float s = ps[t], d = pd[t], o = po[t];
            ss += s * s; sd += s * d; so += s * o;
            dd2 += d * d; dpo += d * o; oo += o * o;
            ns &= (s != 0.f); nd &= (d != 0.f); no &= (o != 0.f);
        }
#pragma unroll
        for (int o = 16; o; o >>= 1) {
            ss  += __shfl_xor_sync(0xffffffffu, ss,  o);
            sd  += __shfl_xor_sync(0xffffffffu, sd,  o);
            so  += __shfl_xor_sync(0xffffffffu, so,  o);
            dd2 += __shfl_xor_sync(0xffffffffu, dd2, o);
            dpo += __shfl_xor_sync(0xffffffffu, dpo, o);
            oo  += __shfl_xor_sync(0xffffffffu, oo,  o);
        }
        const bool ans = __all_sync(0xffffffffu, ns);
        const bool and_ = __all_sync(0xffffffffu, nd);
        const bool ano = __all_sync(0xffffffffu, no);
        if (lane == 0) {
            g_nz[0] = ans; g_nz[1] = and_; g_nz[2] = ano;
            g_G[0] = ss; g_G[1] = sd; g_G[2] = so;
            g_G[3] = dd2; g_G[4] = dpo; g_G[5] = oo;
        }
    }
    const int n = blockIdx.x * blockDim.x + threadIdx.x;
    if (n < NN) { g_c[n] = 0.0f; g_deg[n] = 0.0f; }
}

// ---------------------------------------------------------------------------
// K1: octet-per-edge (4 edges/warp). Norms inline (same shuffle tree as the
// old k_pre => bitwise-identical e). raw dot -> g_dot; scaled scatter-add.
// ---------------------------------------------------------------------------
__global__ void k_edge_dot(const float* __restrict__ x,
                           const int* __restrict__ ei) {
    const int warp = (blockIdx.x * blockDim.x + threadIdx.x) >> 5;
    const int lane = threadIdx.x & 31;
    const int oct  = lane >> 3, ol = lane & 7;
    const int eid  = warp * 4 + oct;
    if (eid >= EE) return;

    const int r = ei[eid];
    const int c = ei[EE + eid];
    const float4* xr = reinterpret_cast<const float4*>(x) + (size_t)r * 32;
    const float4* xc = reinterpret_cast<const float4*>(x) + (size_t)c * 32;

    float s = 0.f, srr = 0.f, scc = 0.f;
#pragma unroll
    for (int i = 0; i < 4; i++) {
        const int k = i * 8 + ol;
        const float4 a = xr[k];
        const float4 b = xc[k];
        s   += a.x * b.x + a.y * b.y + a.z * b.z + a.w * b.w;
        srr += a.x * a.x + a.y * a.y + a.z * a.z + a.w * a.w;
        scc += b.x * b.x + b.y * b.y + b.z * b.z + b.w * b.w;
    }
#pragma unroll
    for (int o = 4; o; o >>= 1) {
        s   += __shfl_xor_sync(0xffffffffu, s,   o);
        srr += __shfl_xor_sync(0xffffffffu, srr, o);
        scc += __shfl_xor_sync(0xffffffffu, scc, o);
    }

    if (ol == 0) {
        g_dot[eid] = s;
        // e = s * inv_r * inv_c with inv = 1/sqrtf(ssq): same ops/order as before
        const float e = s * (1.0f / sqrtf(srr)) * (1.0f / sqrtf(scc));
        atomicAdd(&g_c[c], e);
        atomicAdd(&g_deg[c], 1.0f);
    }
}

// ---------------------------------------------------------------------------
// K2: octet-per-node. class -> xout = x + f; prompt dots (for record p) and
// exact ||x_new||^2 accumulated in the SAME loop; writes 16B record
// (p = w + 0.5*G*cf, rn with cls packed in 3 LSBs).
// ---------------------------------------------------------------------------
__global__ void k_addf(const float* __restrict__ x,
                       const float* __restrict__ ps,
                       const float* __restrict__ pd,
                       const float* __restrict__ po,
                       float* __restrict__ xout) {
    const int warp = (blockIdx.x * blockDim.x + threadIdx.x) >> 5;
    const int lane = threadIdx.x & 31;
    const int oct  = lane >> 3, ol = lane & 7;
    const int node = warp * 4 + oct;
    if (node >= NN) return;

    const float cacc = g_c[node];
    const float deg  = g_deg[node];
    const bool m_sim = (deg > 0.0f) && (cacc / deg <= SIM_THR);
    const bool m_deg = (deg <= DEG_THR);
    const bool m_oth = !(m_sim || m_deg);
    const int nzs = g_nz[0], nzd = g_nz[1], nzo = g_nz[2];

    // numerator sums ALL masked prompts; plen counts only masked&&all-nonzero
    int cls;
    if (m_oth)               cls = nzo ? 3 : 4;
    else if (m_sim && m_deg) cls = (nzs + nzd == 2) ? 2 : ((nzs + nzd == 1) ? 5 : 4);
    else if (m_sim)          cls = nzs ? 0 : 4;
    else                     cls = nzd ? 1 : 4;
    const float4 cf = c_coef[cls];

    const float4* xr  = reinterpret_cast<const float4*>(x) + (size_t)node * 32;
    float4* xw        = reinterpret_cast<float4*>(xout) + (size_t)node * 32;
    const float4* p4s = reinterpret_cast<const float4*>(ps);
    const float4* p4d = reinterpret_cast<const float4*>(pd);
    const float4* p4o = reinterpret_cast<const float4*>(po);

    float as = 0.f, ad = 0.f, ao = 0.f, nsq = 0.f;
#pragma unroll
    for (int i = 0; i < 4; i++) {
        const int k = i * 8 + ol;
        const float4 v = xr[k];
        const float4 s = p4s[k], d = p4d[k], o = p4o[k];
        float4 xn;
        float fx = cf.x * s.x + cf.y * d.x; fx += cf.z * o.x;
        float fy = cf.x * s.y + cf.y * d.y; fy += cf.z * o.y;
        float fz = cf.x * s.z + cf.y * d.z; fz += cf.z * o.z;
        float fw = cf.x * s.w + cf.y * d.w; fw += cf.z * o.w;
        xn.x = v.x + fx; xn.y = v.y + fy; xn.z = v.z + fz; xn.w = v.w + fw;
        xw[k] = xn;
        as  += v.x * s.x + v.y * s.y + v.z * s.z + v.w * s.w;
        ad  += v.x * d.x + v.y * d.y + v.z * d.z + v.w * d.w;
        ao  += v.x * o.x + v.y * o.y + v.z * o.z + v.w * o.w;
        nsq += xn.x * xn.x + xn.y * xn.y + xn.z * xn.z + xn.w * xn.w;
    }
#pragma unroll
    for (int o = 4; o; o >>= 1) {
        as  += __shfl_xor_sync(0xffffffffu, as,  o);
        ad  += __shfl_xor_sync(0xffffffffu, ad,  o);
        ao  += __shfl_xor_sync(0xffffffffu, ao,  o);
        nsq += __shfl_xor_sync(0xffffffffu, nsq, o);
    }

    if (ol == 0) {
        // G·cf (3x3 symmetric gram packed ss,sd,so,dd,dpo,oo)
        const float gv0 = g_G[0] * cf.x + g_G[1] * cf.y + g_G[2] * cf.z;
        const float gv1 = g_G[1] * cf.x + g_G[3] * cf.y + g_G[4] * cf.z;
        const float gv2 = g_G[2] * cf.x + g_G[4] * cf.y + g_G[5] * cf.z;
        const float rn = 1.0f / fmaxf(sqrtf(nsq), EPS_F);   // exact ||x_new||
        // pack cls into the 3 LSBs of rn's mantissa (<= 2^-21 rel perturbation)
        const unsigned rbits = (__float_as_uint(rn) & ~7u) | (unsigned)cls;
        g_rec[node] = make_float4(as + 0.5f * gv0,
                                  ad + 0.5f * gv1,
                                  ao + 0.5f * gv2,
                                  __uint_as_float(rbits));
    }
}

// ---------------------------------------------------------------------------
// K3: 4 edges per thread (all coalesced; EE = 1024*625 exactly, no bounds).
//   ~20 independent loads in flight per thread against the L2-latency wall.
// ---------------------------------------------------------------------------
__global__ void k_prune(const int* __restrict__ ei,
                        float* __restrict__ keep) {
    const int base = blockIdx.x * 1024 + threadIdx.x;
    const int e0 = base, e1 = base + 256, e2 = base + 512, e3 = base + 768;

    const int r0 = ei[e0], c0 = ei[EE + e0];
    const int r1 = ei[e1], c1 = ei[EE + e1];
    const int r2 = ei[e2], c2 = ei[EE + e2];
    const int r3 = ei[e3], c3 = ei[EE + e3];

    const float4 wr0 = g_rec[r0], wc0 = g_rec[c0];
    const float4 wr1 = g_rec[r1], wc1 = g_rec[c1];
    const float4 wr2 = g_rec[r2], wc2 = g_rec[c2];
    const float4 wr3 = g_rec[r3], wc3 = g_rec[c3];

    const float d0 = g_dot[e0], d1 = g_dot[e1];
    const float d2 = g_dot[e2], d3 = g_dot[e3];

    const float4 fr0 = c_coef[__float_as_uint(wr0.w) & 7u];
    const float4 fc0 = c_coef[__float_as_uint(wc0.w) & 7u];
    const float4 fr1 = c_coef[__float_as_uint(wr1.w) & 7u];
    const float4 fc1 = c_coef[__float_as_uint(wc1.w) & 7u];
    const float4 fr2 = c_coef[__float_as_uint(wr2.w) & 7u];
    const float4 fc2 = c_coef[__float_as_uint(wc2.w) & 7u];
    const float4 fr3 = c_coef[__float_as_uint(wr3.w) & 7u];
    const float4 fc3 = c_coef[__float_as_uint(wc3.w) & 7u];

    float n0 = d0 + fc0.x * wr0.x + fc0.y * wr0.y + fc0.z * wr0.z
                  + fr0.x * wc0.x + fr0.y * wc0.y + fr0.z * wc0.z;
    float n1 = d1 + fc1.x * wr1.x + fc1.y * wr1.y + fc1.z * wr1.z
                  + fr1.x * wc1.x + fr1.y * wc1.y + fr1.z * wc1.z;
    float n2 = d2 + fc2.x * wr2.x + fc2.y * wr2.y + fc2.z * wr2.z
                  + fr2.x * wc2.x + fr2.y * wc2.y + fr2.z * wc2.z;
    float n3 = d3 + fc3.x * wr3.x + fc3.y * wr3.y + fc3.z * wr3.z
                  + fr3.x * wc3.x + fr3.y * wc3.y + fr3.z * wc3.z;

    keep[e0] = (n0 * wr0.w * wc0.w >= PT_THR) ? 1.0f : 0.0f;
    keep[e1] = (n1 * wr1.w * wc1.w >= PT_THR) ? 1.0f : 0.0f;
    keep[e2] = (n2 * wr2.w * wc2.w >= PT_THR) ? 1.0f : 0.0f;
    keep[e3] = (n3 * wr3.w * wc3.w >= PT_THR) ? 1.0f : 0.0f;
}

// ---------------------------------------------------------------------------
extern "C" void kernel_launch(void* const* d_in, const int* in_sizes, int n_in,
                              void* d_out, int out_size) {
    const float* x  = (const float*)d_in[0];
    const int*   ei = (const int*)d_in[1];
    const float* ps = (const float*)d_in[2];
    const float* pd = (const float*)d_in[3];
    const float* po = (const float*)d_in[4];

    float* xout = (float*)d_out;
    float* keep = xout + (size_t)NN * DD;

    const int TPB = 256;
    const int per_blk = (TPB / 32) * 4;   // 32 nodes or edges per block

    k_init<<<(NN + TPB - 1) / TPB, TPB>>>(ps, pd, po);
    k_edge_dot<<<(EE + per_blk - 1) / per_blk, TPB>>>(x, ei);
    k_addf<<<(NN + per_blk - 1) / per_blk, TPB>>>(x, ps, pd, po, xout);
    k_prune<<<EE / 1024, TPB>>>(ei, keep);
}